// round 6
// baseline (speedup 1.0000x reference)
#include <cuda_runtime.h>

// BoxModelTriples, m-phased for L2 residency, fused finalize.
// box: (M=8, B=200000, 2, D=32) f32 -> 64 floats (256 B) per (m, idx) row,
//      z at +0, Z at +128 B. Each m-slab is B*256B = 51.2 MB < 126 MB L2.
// ids: (N, 4) int32. out: (N,) f32.
//
// Single main kernel, grid (chunks, 8): blockIdx.y = m (slow raster dim =>
// slab-phased execution keeps each 51.2 MB slab L2-resident while gathered).
// Each block: 8 warps x 4 queries = 32 queries, one m. Lane loads float4 z/Z
// for A,B,C (6x LDG.128), partial side products, xor-reduce over 8 dim-lanes,
// stores UNWEIGHTED {volA, volAB, volABC} as one float4 per (m, n).
// Then: __threadfence + atomicAdd on the chunk counter; the 8th arriver
// re-reads the 8 m-partials for its 32 queries (L2-hot), applies inline
// softmax weights, sums in fixed m order (bitwise deterministic), applies
// the mask logic, and writes out. Counter uses a mod-8 trick so it never
// needs zeroing: every call adds exactly 8 per chunk.

#define TINYF 1.17549435e-38f
#define MAXN  100096
#define MAXCHUNK 4096

__device__ float4 g_P[8 * MAXN];          // [m * N + n] = {volA, volAB, volABC, 0}
__device__ unsigned int g_cnt[MAXCHUNK];  // arrival counters (mod-8 semantics)

__device__ __forceinline__ void side_step(float az, float aZ,
                                          float bz, float bZ,
                                          float cz, float cZ,
                                          float& pA, float& pAB, float& pABC) {
    float a0 = __saturatef(az), a1 = __saturatef(aZ);
    float b0 = __saturatef(bz), b1 = __saturatef(bZ);
    float c0 = __saturatef(cz), c1 = __saturatef(cZ);
    pA *= fmaxf(a1 - a0, 0.0f);
    float z = fmaxf(a0, b0);
    float Z = fminf(a1, b1);
    pAB *= fmaxf(Z - z, 0.0f);
    z = fmaxf(z, c0);
    Z = fminf(Z, c1);
    pABC *= fmaxf(Z - z, 0.0f);
}

__global__ void __launch_bounds__(256)
phase_fused_kernel(const float* __restrict__ box,
                   const float* __restrict__ w,
                   const int* __restrict__ ids,
                   float* __restrict__ out,
                   int N, int B) {
    int m     = blockIdx.y;                      // slow raster dim -> phased
    int chunk = blockIdx.x;
    int lane  = threadIdx.x & 31;
    int warp  = threadIdx.x >> 5;                // 0..7
    int qq    = lane >> 3;                       // query within warp, 0..3
    int d     = lane & 7;                        // dim group, dims [4d, 4d+4)

    int n  = (chunk * 8 + warp) * 4 + qq;
    int nc = n < N ? n : N - 1;                  // clamp loads, predicate store

    int4 id = *(const int4*)(ids + 4 * nc);

    size_t mb = (size_t)m * (size_t)B;
    const float* pAp = box + (mb + (size_t)id.x) * 64 + d * 4;
    const float* pBp = box + (mb + (size_t)id.y) * 64 + d * 4;
    const float* pCp = box + (mb + (size_t)id.z) * 64 + d * 4;

    float4 az = *(const float4*)(pAp);
    float4 aZ = *(const float4*)(pAp + 32);
    float4 bz = *(const float4*)(pBp);
    float4 bZ = *(const float4*)(pBp + 32);
    float4 cz = *(const float4*)(pCp);
    float4 cZ = *(const float4*)(pCp + 32);

    float pA = 1.0f, pAB = 1.0f, pABC = 1.0f;
    side_step(az.x, aZ.x, bz.x, bZ.x, cz.x, cZ.x, pA, pAB, pABC);
    side_step(az.y, aZ.y, bz.y, bZ.y, cz.y, cZ.y, pA, pAB, pABC);
    side_step(az.z, aZ.z, bz.z, bZ.z, cz.z, cZ.z, pA, pAB, pABC);
    side_step(az.w, aZ.w, bz.w, bZ.w, cz.w, cZ.w, pA, pAB, pABC);

    // Product-reduce across the 8 dim-lanes of this query (xor 1, 2, 4).
    #pragma unroll
    for (int off = 1; off <= 4; off <<= 1) {
        pA   *= __shfl_xor_sync(0xFFFFFFFFu, pA,   off);
        pAB  *= __shfl_xor_sync(0xFFFFFFFFu, pAB,  off);
        pABC *= __shfl_xor_sync(0xFFFFFFFFu, pABC, off);
    }

    if (d == 0 && n < N) {
        g_P[(size_t)m * N + n] = make_float4(pA, pAB, pABC, 0.0f);
    }

    // ---- arrival + last-block finalize ----
    __syncthreads();                 // all stores in this block issued
    __shared__ unsigned int s_old;
    if (threadIdx.x == 0) {
        __threadfence();             // release partials to GPU scope
        s_old = atomicAdd(&g_cnt[chunk], 1u);
    }
    __syncthreads();
    if ((s_old & 7u) != 7u) return;  // not the last arriver for this chunk

    // Finalize 32 queries: tid = q*8 + mm; 8 lane-aligned threads per query.
    int q  = threadIdx.x >> 3;       // 0..31
    int mm = threadIdx.x & 7;        // 0..7
    int fn = chunk * 32 + q;
    if (fn >= N) return;

    // Inline softmax over the 8 weights (L1-broadcast, trivial).
    float wv[8];
    float mx = -3.0e38f;
    #pragma unroll
    for (int k = 0; k < 8; k++) { wv[k] = w[k]; mx = fmaxf(mx, wv[k]); }
    float ssum = 0.0f;
    #pragma unroll
    for (int k = 0; k < 8; k++) { wv[k] = expf(wv[k] - mx); ssum += wv[k]; }
    float wm = wv[mm] / ssum;

    float4 p = g_P[(size_t)mm * N + fn];   // L2-hot (just written)
    float sA = wm * p.x, sAB = wm * p.y, sABC = wm * p.z;

    // Sum over m in fixed xor order (deterministic), groups of 8 lanes.
    #pragma unroll
    for (int off = 1; off <= 4; off <<= 1) {
        sA   += __shfl_xor_sync(0xFFFFFFFFu, sA,   off);
        sAB  += __shfl_xor_sync(0xFFFFFFFFu, sAB,  off);
        sABC += __shfl_xor_sync(0xFFFFFFFFu, sABC, off);
    }

    if (mm == 0) {
        int4 fid = *(const int4*)(ids + 4 * fn);
        float res;
        if (fid.y != fid.z) {
            res = (sABC + TINYF) / (sAB + TINYF);      // three_cond
        } else if (fid.x == fid.y) {
            res = sA;                                   // unary
        } else {
            res = (sAB + TINYF) / (sA + TINYF);         // two_cond
        }
        out[fn] = res;
    }
}

extern "C" void kernel_launch(void* const* d_in, const int* in_sizes, int n_in,
                              void* d_out, int out_size) {
    const float* box = (const float*)d_in[0];
    const float* w   = (const float*)d_in[1];
    const int*   ids = (const int*)d_in[2];
    float*       out = (float*)d_out;

    int Mw = in_sizes[1];                 // 8
    int N  = in_sizes[2] / 4;             // 100000
    int B  = (int)((long long)in_sizes[0] / ((long long)Mw * 64));  // 200000

    // 32 queries per block (8 warps x 4 queries), m on grid.y (slow).
    int chunks = (N + 31) / 32;           // 3125 <= MAXCHUNK
    phase_fused_kernel<<<dim3(chunks, 8), 256>>>(box, w, ids, out, N, B);
}

// round 7
// speedup vs baseline: 1.2572x; 1.2572x over previous
#include <cuda_runtime.h>

// BoxModelTriples, m-phased for L2 residency (two kernels; R5 structure,
// reduce kernel de-MUFU'd via per-block shared softmax).
// box: (M=8, B=200000, 2, D=32) f32 -> 64 floats (256 B) per (m, idx) row,
//      z at +0, Z at +128 B. Each m-slab is B*256B = 51.2 MB < 126 MB L2.
// ids: (N, 4) int32. out: (N,) f32.
//
// Kernel 1 (phase): blockIdx.y = m (slow raster dim => slab-phased execution
//   keeps each 51.2 MB slab L2-resident while it is being gathered).
//   warp = 4 queries; per query 8 lanes, 4 dims each. Lane loads float4 z/Z
//   for A,B,C (6x LDG.128), partial side products, xor-reduce over 8 lanes,
//   writes UNWEIGHTED {volA, volAB, volABC} as one float4 per (m, n).
// Kernel 2 (reduce): softmax(w) computed ONCE per block into smem (8 expf
//   per block instead of 8 per thread -> kills the MUFU bottleneck), then
//   weighted sum over the 8 m-partials in fixed order, mask logic, write out.

#define TINYF 1.17549435e-38f
#define MAXN  100096

__device__ float4 g_P[8 * MAXN];   // [m * N + n] = {volA, volAB, volABC, 0}

__device__ __forceinline__ void side_step(float az, float aZ,
                                          float bz, float bZ,
                                          float cz, float cZ,
                                          float& pA, float& pAB, float& pABC) {
    float a0 = __saturatef(az), a1 = __saturatef(aZ);
    float b0 = __saturatef(bz), b1 = __saturatef(bZ);
    float c0 = __saturatef(cz), c1 = __saturatef(cZ);
    pA *= fmaxf(a1 - a0, 0.0f);
    float z = fmaxf(a0, b0);
    float Z = fminf(a1, b1);
    pAB *= fmaxf(Z - z, 0.0f);
    z = fmaxf(z, c0);
    Z = fminf(Z, c1);
    pABC *= fmaxf(Z - z, 0.0f);
}

__global__ void __launch_bounds__(256)
phase_kernel(const float* __restrict__ box,
             const int* __restrict__ ids,
             int N, int B) {
    int m    = blockIdx.y;                       // slow raster dim -> phased
    int lane = threadIdx.x & 31;
    int warp = threadIdx.x >> 5;                 // 0..7
    int qq   = lane >> 3;                        // query within warp, 0..3
    int d    = lane & 7;                         // dim group, dims [4d, 4d+4)

    int n = (blockIdx.x * 8 + warp) * 4 + qq;
    int nc = n < N ? n : N - 1;                  // clamp loads, predicate store

    int4 id = *(const int4*)(ids + 4 * nc);

    size_t mb = (size_t)m * (size_t)B;
    const float* pAp = box + (mb + (size_t)id.x) * 64 + d * 4;
    const float* pBp = box + (mb + (size_t)id.y) * 64 + d * 4;
    const float* pCp = box + (mb + (size_t)id.z) * 64 + d * 4;

    float4 az = *(const float4*)(pAp);
    float4 aZ = *(const float4*)(pAp + 32);
    float4 bz = *(const float4*)(pBp);
    float4 bZ = *(const float4*)(pBp + 32);
    float4 cz = *(const float4*)(pCp);
    float4 cZ = *(const float4*)(pCp + 32);

    float pA = 1.0f, pAB = 1.0f, pABC = 1.0f;
    side_step(az.x, aZ.x, bz.x, bZ.x, cz.x, cZ.x, pA, pAB, pABC);
    side_step(az.y, aZ.y, bz.y, bZ.y, cz.y, cZ.y, pA, pAB, pABC);
    side_step(az.z, aZ.z, bz.z, bZ.z, cz.z, cZ.z, pA, pAB, pABC);
    side_step(az.w, aZ.w, bz.w, bZ.w, cz.w, cZ.w, pA, pAB, pABC);

    // Product-reduce across the 8 dim-lanes of this query (xor 1, 2, 4).
    #pragma unroll
    for (int off = 1; off <= 4; off <<= 1) {
        pA   *= __shfl_xor_sync(0xFFFFFFFFu, pA,   off);
        pAB  *= __shfl_xor_sync(0xFFFFFFFFu, pAB,  off);
        pABC *= __shfl_xor_sync(0xFFFFFFFFu, pABC, off);
    }

    if (d == 0 && n < N) {
        g_P[(size_t)m * N + n] = make_float4(pA, pAB, pABC, 0.0f);
    }
}

__global__ void __launch_bounds__(128)
reduce_kernel(const float* __restrict__ w,
              const int* __restrict__ ids,
              float* __restrict__ out, int N) {
    // Softmax over the 8 weights once per block (smem broadcast).
    __shared__ float s_w[8];
    if (threadIdx.x < 8) {
        float x = w[threadIdx.x];
        float mx = x;
        #pragma unroll
        for (int off = 4; off; off >>= 1)
            mx = fmaxf(mx, __shfl_xor_sync(0x000000FFu, mx, off));
        float e = expf(x - mx);
        float s = e;
        #pragma unroll
        for (int off = 4; off; off >>= 1)
            s += __shfl_xor_sync(0x000000FFu, s, off);
        s_w[threadIdx.x] = e / s;
    }
    __syncthreads();

    int n = blockIdx.x * blockDim.x + threadIdx.x;
    if (n >= N) return;

    float sA = 0.0f, sAB = 0.0f, sABC = 0.0f;
    #pragma unroll
    for (int m = 0; m < 8; m++) {
        float4 p = g_P[(size_t)m * N + n];
        float wm = s_w[m];
        sA   += wm * p.x;
        sAB  += wm * p.y;
        sABC += wm * p.z;
    }

    int4 id = *(const int4*)(ids + 4 * n);

    float res;
    if (id.y != id.z) {
        res = (sABC + TINYF) / (sAB + TINYF);      // three_cond
    } else if (id.x == id.y) {
        res = sA;                                   // unary
    } else {
        res = (sAB + TINYF) / (sA + TINYF);         // two_cond
    }
    out[n] = res;
}

extern "C" void kernel_launch(void* const* d_in, const int* in_sizes, int n_in,
                              void* d_out, int out_size) {
    const float* box = (const float*)d_in[0];
    const float* w   = (const float*)d_in[1];
    const int*   ids = (const int*)d_in[2];
    float*       out = (float*)d_out;

    int Mw = in_sizes[1];                 // 8
    int N  = in_sizes[2] / 4;             // 100000
    int B  = (int)((long long)in_sizes[0] / ((long long)Mw * 64));  // 200000

    // 32 queries per block (8 warps x 4 queries), m on grid.y (slow).
    int chunks = (N + 31) / 32;
    phase_kernel<<<dim3(chunks, 8), 256>>>(box, ids, N, B);

    reduce_kernel<<<(N + 127) / 128, 128>>>(w, ids, out, N);
}